// round 3
// baseline (speedup 1.0000x reference)
#include <cuda_runtime.h>
#include <float.h>

// CRF constituency marginals via inside-outside.
// B=8, S=256. scores: [B,S,S] f32. mask ignored (always full triu, lens = S-1).
//
// Inside (log space):   alpha[i,j] = s[i,j] + LSE_{i<k<j}(alpha[i,k]+alpha[k,j])
// Outside (prob space): mu[i,j] accumulated by scatter from parents:
//   parent (i,b), split k: v = mu[i,b] * exp(alpha[i,k]+alpha[k,b]-(alpha[i,b]-s[i,b]))
//   -> accL[i,k] += v ; accRT[b,k] += v        (mu[p,q] = accL[p,q] + accRT[q,p])
// No atomics needed: within one width step each accL row i / accRT row b is
// owned by exactly one parent block. Deterministic.

constexpr int Bb = 8;
constexpr int Ss = 256;
constexpr int NN = Ss * Ss;

__device__ float g_A[Bb * NN];     // alpha
__device__ float g_AT[Bb * NN];    // alpha transposed (AT[j][i] = A[i][j])
__device__ float g_accL[Bb * NN];  // left-child contributions (row = i)
__device__ float g_accRT[Bb * NN]; // right-child contributions, transposed (row = j)

__device__ __forceinline__ float warpMax(float v) {
#pragma unroll
    for (int o = 16; o; o >>= 1) v = fmaxf(v, __shfl_xor_sync(0xffffffffu, v, o));
    return v;
}
__device__ __forceinline__ float warpSum(float v) {
#pragma unroll
    for (int o = 16; o; o >>= 1) v += __shfl_xor_sync(0xffffffffu, v, o);
    return v;
}

__global__ void init_kernel(const float* __restrict__ scores) {
    int idx = blockIdx.x * blockDim.x + threadIdx.x;
    if (idx >= Bb * NN) return;
    int b = idx >> 16, r = idx & 65535, i = r >> 8, j = r & 255;
    float z = 0.f;
    if (i == 0 && j == Ss - 1) z = 1.f;  // mu at root = 1
    g_accL[idx] = z;
    g_accRT[idx] = 0.f;
    if (j == i + 1) {  // width-1 spans: alpha = score
        float v = scores[idx];
        g_A[idx] = v;
        g_AT[(b << 16) + (j << 8) + i] = v;
    }
}

__global__ __launch_bounds__(128) void inside_step(const float* __restrict__ scores, int w) {
    int cells = Ss - w;
    int b = blockIdx.x / cells;
    int i = blockIdx.x - b * cells;
    int j = i + w;
    const float* A  = g_A  + (b << 16);
    const float* AT = g_AT + (b << 16);
    int t = threadIdx.x;
    // terms k = i+1 .. j-1  (w-1 <= 254 terms -> at most 2 per thread)
    int k0 = i + 1 + t;
    int k1 = k0 + 128;
    float v0 = -FLT_MAX, v1 = -FLT_MAX;
    if (k0 < j) v0 = A[(i << 8) + k0] + AT[(j << 8) + k0];
    if (k1 < j) v1 = A[(i << 8) + k1] + AT[(j << 8) + k1];
    float m = fmaxf(v0, v1);
    m = warpMax(m);
    __shared__ float sred[4];
    if ((t & 31) == 0) sred[t >> 5] = m;
    __syncthreads();
    m = fmaxf(fmaxf(sred[0], sred[1]), fmaxf(sred[2], sred[3]));
    float s = __expf(v0 - m) + __expf(v1 - m);  // padded lanes underflow to 0
    s = warpSum(s);
    __syncthreads();
    if ((t & 31) == 0) sred[t >> 5] = s;
    __syncthreads();
    if (t == 0) {
        float tot = (sred[0] + sred[1]) + (sred[2] + sred[3]);
        float r = scores[(b << 16) + (i << 8) + j] + m + __logf(tot);
        g_A[(b << 16) + (i << 8) + j] = r;
        g_AT[(b << 16) + (j << 8) + i] = r;
    }
}

__global__ __launch_bounds__(128) void outside_step(const float* __restrict__ scores, int w) {
    int cells = Ss - w;
    int b = blockIdx.x / cells;
    int i = blockIdx.x - b * cells;
    int j = i + w;
    int ij = (b << 16) + (i << 8) + j;
    float mu = g_accL[ij] + g_accRT[(b << 16) + (j << 8) + i];
    if (mu == 0.f) return;  // uniform across block; exact (all contributions 0)
    float lse = g_A[ij] - scores[ij];  // = LSE over splits; exponents below <= 0
    const float* A  = g_A  + (b << 16);
    const float* AT = g_AT + (b << 16);
    float* aL  = g_accL  + (b << 16);
    float* aRT = g_accRT + (b << 16);
    int t = threadIdx.x;
#pragma unroll
    for (int rep = 0; rep < 2; rep++) {
        int k = i + 1 + t + (rep << 7);
        if (k < j) {
            float v = mu * __expf(A[(i << 8) + k] + AT[(j << 8) + k] - lse);
            aL[(i << 8) + k]  += v;  // row i owned by this block this step
            aRT[(j << 8) + k] += v;  // row j owned by this block this step
        }
    }
}

__global__ void finalize_kernel(float* __restrict__ out) {
    int idx = blockIdx.x * blockDim.x + threadIdx.x;
    if (idx >= Bb * NN) return;
    int b = idx >> 16, r = idx & 65535, i = r >> 8, j = r & 255;
    float v = 0.f;
    if (j > i) v = g_accL[idx] + g_accRT[(b << 16) + (j << 8) + i];
    out[idx] = v;
}

extern "C" void kernel_launch(void* const* d_in, const int* in_sizes, int n_in,
                              void* d_out, int out_size) {
    const float* scores = (const float*)d_in[0];
    float* out = (float*)d_out;

    init_kernel<<<(Bb * NN + 255) / 256, 256>>>(scores);

    for (int w = 2; w <= Ss - 1; w++)
        inside_step<<<Bb * (Ss - w), 128>>>(scores, w);

    for (int w = Ss - 1; w >= 2; w--)
        outside_step<<<Bb * (Ss - w), 128>>>(scores, w);

    finalize_kernel<<<(Bb * NN + 255) / 256, 256>>>(out);
}

// round 6
// speedup vs baseline: 1.0007x; 1.0007x over previous
#include <cuda_runtime.h>
#include <float.h>

// CRF constituency marginals via inside-outside.
// B=8, S=256. scores: [B,S,S] f32. mask ignored (always full triu, lens = S-1).
//
// Inside (log space):   alpha[i,j] = s[i,j] + LSE_{i<k<j}(alpha[i,k]+alpha[k,j])
// Outside (prob space): mu[i,j] accumulated by scatter from parents:
//   parent (i,b), split k: v = mu[i,b] * exp(alpha[i,k]+alpha[k,b]-(alpha[i,b]-s[i,b]))
//   -> accL[i,k] += v ; accRT[b,k] += v        (mu[p,q] = accL[p,q] + accRT[q,p])
// No atomics needed: within one width step each accL row i / accRT row b is
// owned by exactly one parent block. Deterministic.

constexpr int Bb = 8;
constexpr int Ss = 256;
constexpr int NN = Ss * Ss;

__device__ float g_A[Bb * NN];     // alpha
__device__ float g_AT[Bb * NN];    // alpha transposed (AT[j][i] = A[i][j])
__device__ float g_accL[Bb * NN];  // left-child contributions (row = i)
__device__ float g_accRT[Bb * NN]; // right-child contributions, transposed (row = j)

__device__ __forceinline__ float warpMax(float v) {
#pragma unroll
    for (int o = 16; o; o >>= 1) v = fmaxf(v, __shfl_xor_sync(0xffffffffu, v, o));
    return v;
}
__device__ __forceinline__ float warpSum(float v) {
#pragma unroll
    for (int o = 16; o; o >>= 1) v += __shfl_xor_sync(0xffffffffu, v, o);
    return v;
}

__global__ void init_kernel(const float* __restrict__ scores) {
    int idx = blockIdx.x * blockDim.x + threadIdx.x;
    if (idx >= Bb * NN) return;
    int b = idx >> 16, r = idx & 65535, i = r >> 8, j = r & 255;
    float z = 0.f;
    if (i == 0 && j == Ss - 1) z = 1.f;  // mu at root = 1
    g_accL[idx] = z;
    g_accRT[idx] = 0.f;
    if (j == i + 1) {  // width-1 spans: alpha = score
        float v = scores[idx];
        g_A[idx] = v;
        g_AT[(b << 16) + (j << 8) + i] = v;
    }
}

__global__ __launch_bounds__(128) void inside_step(const float* __restrict__ scores, int w) {
    int cells = Ss - w;
    int b = blockIdx.x / cells;
    int i = blockIdx.x - b * cells;
    int j = i + w;
    const float* A  = g_A  + (b << 16);
    const float* AT = g_AT + (b << 16);
    int t = threadIdx.x;
    // terms k = i+1 .. j-1  (w-1 <= 254 terms -> at most 2 per thread)
    int k0 = i + 1 + t;
    int k1 = k0 + 128;
    float v0 = -FLT_MAX, v1 = -FLT_MAX;
    if (k0 < j) v0 = A[(i << 8) + k0] + AT[(j << 8) + k0];
    if (k1 < j) v1 = A[(i << 8) + k1] + AT[(j << 8) + k1];
    float m = fmaxf(v0, v1);
    m = warpMax(m);
    __shared__ float sred[4];
    if ((t & 31) == 0) sred[t >> 5] = m;
    __syncthreads();
    m = fmaxf(fmaxf(sred[0], sred[1]), fmaxf(sred[2], sred[3]));
    float s = __expf(v0 - m) + __expf(v1 - m);  // padded lanes underflow to 0
    s = warpSum(s);
    __syncthreads();
    if ((t & 31) == 0) sred[t >> 5] = s;
    __syncthreads();
    if (t == 0) {
        float tot = (sred[0] + sred[1]) + (sred[2] + sred[3]);
        float r = scores[(b << 16) + (i << 8) + j] + m + __logf(tot);
        g_A[(b << 16) + (i << 8) + j] = r;
        g_AT[(b << 16) + (j << 8) + i] = r;
    }
}

__global__ __launch_bounds__(128) void outside_step(const float* __restrict__ scores, int w) {
    int cells = Ss - w;
    int b = blockIdx.x / cells;
    int i = blockIdx.x - b * cells;
    int j = i + w;
    int ij = (b << 16) + (i << 8) + j;
    float mu = g_accL[ij] + g_accRT[(b << 16) + (j << 8) + i];
    if (mu == 0.f) return;  // uniform across block; exact (all contributions 0)
    float lse = g_A[ij] - scores[ij];  // = LSE over splits; exponents below <= 0
    const float* A  = g_A  + (b << 16);
    const float* AT = g_AT + (b << 16);
    float* aL  = g_accL  + (b << 16);
    float* aRT = g_accRT + (b << 16);
    int t = threadIdx.x;
#pragma unroll
    for (int rep = 0; rep < 2; rep++) {
        int k = i + 1 + t + (rep << 7);
        if (k < j) {
            float v = mu * __expf(A[(i << 8) + k] + AT[(j << 8) + k] - lse);
            aL[(i << 8) + k]  += v;  // row i owned by this block this step
            aRT[(j << 8) + k] += v;  // row j owned by this block this step
        }
    }
}

__global__ void finalize_kernel(float* __restrict__ out) {
    int idx = blockIdx.x * blockDim.x + threadIdx.x;
    if (idx >= Bb * NN) return;
    int b = idx >> 16, r = idx & 65535, i = r >> 8, j = r & 255;
    float v = 0.f;
    if (j > i) v = g_accL[idx] + g_accRT[(b << 16) + (j << 8) + i];
    out[idx] = v;
}

extern "C" void kernel_launch(void* const* d_in, const int* in_sizes, int n_in,
                              void* d_out, int out_size) {
    const float* scores = (const float*)d_in[0];
    float* out = (float*)d_out;

    init_kernel<<<(Bb * NN + 255) / 256, 256>>>(scores);

    for (int w = 2; w <= Ss - 1; w++)
        inside_step<<<Bb * (Ss - w), 128>>>(scores, w);

    for (int w = Ss - 1; w >= 2; w--)
        outside_step<<<Bb * (Ss - w), 128>>>(scores, w);

    finalize_kernel<<<(Bb * NN + 255) / 256, 256>>>(out);
}

// round 7
// speedup vs baseline: 1.2314x; 1.2305x over previous
#include <cuda_runtime.h>
#include <float.h>

// Blocked CYK inside-outside, T=8 tiles, 32 tile-diagonals each direction.
// B=8, S=256, full upper-triangular mask (lens = 255, root = (0,255)).
//
// Inside (log space):  A[i,j] = s[i,j] + LSE_{i<k<j}(A[i,k] + A[k,j])
// L[i,j] = A[i,j] - s[i,j]  (the LSE over splits of the parent)
// Outside (prob space, GATHER — exponents <= 0, no atomics, deterministic):
//   mu[p,q] = [root] + sum_{b>q} mu[p,b]*exp(A[p,q]+A[q,b]-L[p,b])
//                    + sum_{a<p} mu[a,q]*exp(A[a,p]+A[p,q]-L[a,q])
//
// One block (64 threads) per 8x8 tile. Middle tiles K are bulk-accumulated
// from shared memory; intra-tile dependencies resolved by a 15-step
// micro-diagonal sweep with __syncthreads.

constexpr int Bb = 8;
constexpr int Ss = 256;
constexpr int NN = Ss * Ss;

__device__ float g_A  [Bb * NN];  // inside alpha
__device__ float g_AT [Bb * NN];  // alpha transposed
__device__ float g_L  [Bb * NN];  // alpha - score
__device__ float g_LT [Bb * NN];  // transposed
__device__ float g_mu [Bb * NN];  // marginals
__device__ float g_muT[Bb * NN];  // transposed

__device__ __forceinline__ void lse_update(float v, float& mx, float& s) {
    float nm = fmaxf(mx, v);
    s = s * __expf(mx - nm) + __expf(v - nm);
    mx = nm;
}

__global__ void zero_out_kernel(float* __restrict__ out) {
    int idx = blockIdx.x * blockDim.x + threadIdx.x;
    if (idx < Bb * NN) out[idx] = 0.f;
}

// ───────── inside: diagonal tiles (widths 1..7) ─────────
__global__ __launch_bounds__(64) void inside_diag0(const float* __restrict__ scores) {
    int b = blockIdx.x >> 5;
    int I = blockIdx.x & 31;
    int base = b << 16;
    int t = threadIdx.x, il = t >> 3, jl = t & 7;
    int Ib = I * 8;
    __shared__ float ssc[8][9], scur[8][9];
    ssc[il][jl] = scores[base + (Ib + il) * 256 + Ib + jl];
    __syncthreads();
    float r = 0.f;
    bool valid = jl > il;
    for (int w = 1; w <= 7; w++) {
        if (jl - il == w) {
            if (w == 1) r = ssc[il][jl];
            else {
                float mx = -FLT_MAX, s = 0.f;
                for (int k = il + 1; k < jl; k++)
                    lse_update(scur[il][k] + scur[k][jl], mx, s);
                r = ssc[il][jl] + mx + __logf(s);
            }
            scur[il][jl] = r;
        }
        __syncthreads();
    }
    if (valid) {
        int gi = Ib + il, gj = Ib + jl;
        g_A [base + gi * 256 + gj] = r;
        g_AT[base + gj * 256 + gi] = r;
        float Lv = r - ssc[il][jl];
        g_L [base + gi * 256 + gj] = Lv;
        g_LT[base + gj * 256 + gi] = Lv;
    }
}

// ───────── inside: off-diagonal tile phase, tile-diag d >= 1 ─────────
__global__ __launch_bounds__(64) void inside_phase(const float* __restrict__ scores, int d) {
    int tiles = 32 - d;
    int b = blockIdx.x / tiles;
    int I = blockIdx.x - b * tiles;
    int J = I + d;
    int base = b << 16;
    int t = threadIdx.x, il = t >> 3, jl = t & 7;
    int Ib = I * 8, Jb = J * 8;
    __shared__ float sA[8][9], sB[8][9], sII[8][9], sJJ[8][9], scur[8][9];
    sII[il][jl] = g_A[base + (Ib + il) * 256 + Ib + jl];
    sJJ[il][jl] = g_A[base + (Jb + il) * 256 + Jb + jl];
    // bulk middle tiles K: I < K < J
    float mx = -FLT_MAX, s = 0.f;
    for (int K = I + 1; K < J; K++) {
        __syncthreads();
        sA[il][jl] = g_A [base + (Ib + il) * 256 + K * 8 + jl];  // A[i,k]
        sB[il][jl] = g_AT[base + (Jb + il) * 256 + K * 8 + jl];  // A[k,j]
        __syncthreads();
        float v[8]; float mloc = -FLT_MAX;
#pragma unroll
        for (int k = 0; k < 8; k++) { v[k] = sA[il][k] + sB[jl][k]; mloc = fmaxf(mloc, v[k]); }
        float nm = fmaxf(mx, mloc);
        float acc = s * __expf(mx - nm);
#pragma unroll
        for (int k = 0; k < 8; k++) acc += __expf(v[k] - nm);
        s = acc; mx = nm;
    }
    __syncthreads();
    // intra-tile micro-diagonal sweep
    float sc = scores[base + (Ib + il) * 256 + Jb + jl];
    float r = 0.f;
    int md_self = (7 - il) + jl;
    for (int md = 0; md < 15; md++) {
        if (md_self == md) {
            for (int k = il + 1; k < 8; k++) lse_update(sII[il][k] + scur[k][jl], mx, s);
            for (int k = 0; k < jl; k++)     lse_update(scur[il][k] + sJJ[k][jl], mx, s);
            if (d == 1 && il == 7 && jl == 0) r = sc;          // width-1 cell
            else                              r = sc + mx + __logf(s);
            scur[il][jl] = r;
        }
        __syncthreads();
    }
    int gi = Ib + il, gj = Jb + jl;
    g_A [base + gi * 256 + gj] = r;
    g_AT[base + gj * 256 + gi] = r;
    float Lv = r - sc;
    g_L [base + gi * 256 + gj] = Lv;
    g_LT[base + gj * 256 + gi] = Lv;
}

// ───────── outside: tile phase, tile-diag d (processed 31 -> 0) ─────────
__global__ __launch_bounds__(64) void outside_phase(float* __restrict__ out, int d) {
    int tiles = 32 - d;
    int b = blockIdx.x / tiles;
    int P = blockIdx.x - b * tiles;
    int Q = P + d;
    int base = b << 16;
    int t = threadIdx.x, pl = t >> 3, ql = t & 7;
    int Pb = P * 8, Qb = Q * 8;
    int p = Pb + pl, q = Qb + ql;
    float apq = g_A[base + p * 256 + q];
    float acc = 0.f;
    __shared__ float smu[8][9], sL[8][9], sAx[8][9];
    // left-child role: parents (p,b), b in tiles B > Q
    for (int Bt = Q + 1; Bt < 32; Bt++) {
        __syncthreads();
        smu[pl][ql] = g_mu[base + (Pb + pl) * 256 + Bt * 8 + ql];
        sL [pl][ql] = g_L [base + (Pb + pl) * 256 + Bt * 8 + ql];
        sAx[pl][ql] = g_A [base + (Qb + pl) * 256 + Bt * 8 + ql];
        __syncthreads();
#pragma unroll
        for (int k = 0; k < 8; k++)
            acc += smu[pl][k] * __expf(apq + sAx[ql][k] - sL[pl][k]);
    }
    // right-child role: parents (a,q), a in tiles At < P
    for (int At = 0; At < P; At++) {
        __syncthreads();
        smu[pl][ql] = g_muT[base + (Qb + pl) * 256 + At * 8 + ql];  // mu[a,q]
        sL [pl][ql] = g_LT [base + (Qb + pl) * 256 + At * 8 + ql];  // L[a,q]
        sAx[pl][ql] = g_AT [base + (Pb + pl) * 256 + At * 8 + ql];  // A[a,p]
        __syncthreads();
#pragma unroll
        for (int k = 0; k < 8; k++)
            acc += smu[ql][k] * __expf(sAx[pl][k] + apq - sL[ql][k]);
    }
    __syncthreads();
    // intra-tile sweep: parents within tile row (b in Q) / col (a in P)
    __shared__ float sAQQ[8][9], sAPP[8][9], sLc[8][9], smuc[8][9];
    sAQQ[pl][ql] = g_A[base + (Qb + pl) * 256 + Qb + ql];
    sAPP[pl][ql] = g_A[base + (Pb + pl) * 256 + Pb + ql];
    sLc [pl][ql] = g_L[base + (Pb + pl) * 256 + Qb + ql];
    smuc[pl][ql] = 0.f;
    __syncthreads();
    bool valid = q > p;
    float mu = 0.f;
    int md_self = pl + (7 - ql);
    for (int md = 0; md < 15; md++) {
        if (md_self == md && valid) {
            for (int k = ql + 1; k < 8; k++)
                acc += smuc[pl][k] * __expf(apq + sAQQ[ql][k] - sLc[pl][k]);
            for (int k = 0; k < pl; k++)
                acc += smuc[k][ql] * __expf(sAPP[k][pl] + apq - sLc[k][ql]);
            if (p == 0 && q == 255) acc += 1.f;  // root
            mu = acc;
            smuc[pl][ql] = mu;
        }
        __syncthreads();
    }
    out  [base + p * 256 + q] = mu;
    g_mu [base + p * 256 + q] = mu;
    g_muT[base + q * 256 + p] = mu;
}

extern "C" void kernel_launch(void* const* d_in, const int* in_sizes, int n_in,
                              void* d_out, int out_size) {
    const float* scores = (const float*)d_in[0];
    float* out = (float*)d_out;

    zero_out_kernel<<<(Bb * NN + 255) / 256, 256>>>(out);
    inside_diag0<<<Bb * 32, 64>>>(scores);
    for (int d = 1; d <= 31; d++)
        inside_phase<<<Bb * (32 - d), 64>>>(scores, d);
    for (int d = 31; d >= 0; d--)
        outside_phase<<<Bb * (32 - d), 64>>>(out, d);
}